// round 7
// baseline (speedup 1.0000x reference)
#include <cuda_runtime.h>

#define NB   128
#define CIN  64
#define TDIM 128
#define VV   25
#define RR   8
#define OO   64
#define TVPOS 3200   // TDIM*VV
#define YSTR 640     // padded ysum channel stride (16B-aligned float4 staging)

typedef unsigned long long u64;

// ---- scratch (device globals: no allocation allowed) ----
__device__ float g_part1[NB*4*RR*VV];
__device__ float g_part2[NB*4*RR*VV];
__device__ float g_pstat[NB*4*4];
__device__ float g_ysum[(size_t)NB*OO*YSTR];   // [n][c][640], 625 used

// ---- packed fp32x2 helpers (FFMA2 only reachable via PTX) ----
__device__ __forceinline__ u64 pk2(float a, float b){
    u64 r; asm("mov.b64 %0,{%1,%2};" : "=l"(r) : "f"(a), "f"(b)); return r;
}
__device__ __forceinline__ void upk2(u64 v, float& a, float& b){
    asm("mov.b64 {%0,%1},%2;" : "=f"(a), "=f"(b) : "l"(v));
}
__device__ __forceinline__ void fma2(u64& d, u64 a, u64 b){
    asm("fma.rn.f32x2 %0,%1,%2,%0;" : "+l"(d) : "l"(a), "l"(b));
}

__device__ __forceinline__ int div25(int p){ return (p*1311) >> 15; }  // valid p<256

extern __shared__ char smem_raw[];

// ============================================================
// Kernel A (R3 version, known 61us): stats pass, no atomics.
// grid (4 splits, 128 n), 256 thr.  warp->r, lane->v (lane<25).
// xs natural t-major [ci][t*25+v]; scalar LDS conflict-free.
// ============================================================
__global__ void __launch_bounds__(256, 4) kA(const float* __restrict__ x,
        const float* __restrict__ w1, const float* __restrict__ b1,
        const float* __restrict__ w2, const float* __restrict__ b2)
{
    float2* wz = (float2*)smem_raw;        // [8][64] packed (w1,w2)
    float*  xs = (float*)(wz + 512);       // [64][200]
    float*  red = xs + 12800;              // [8][4]

    int tid = threadIdx.x;
    int split = blockIdx.x, n = blockIdx.y;
    int w = tid >> 5, lane = tid & 31;

    for (int i = tid; i < 512; i += 256)
        wz[i] = make_float2(w1[i], w2[i]);

    float b1r = b1[w], b2r = b2[w];
    float part1 = 0.f, part2 = 0.f, q1 = 0.f, q2 = 0.f;
    const float4* xn4 = (const float4*)(x + (size_t)n*CIN*TVPOS + split*800);
    __syncthreads();

    for (int tile = 0; tile < 4; ++tile) {
        for (int i = tid; i < 3200; i += 256) {
            int ci = i / 50, j = i - ci*50;
            ((float4*)xs)[ci*50 + j] = xn4[ci*800 + tile*50 + j];
        }
        __syncthreads();
        if (lane < 25) {
            float p1[8], p2[8];
            #pragma unroll
            for (int t = 0; t < 8; ++t) { p1[t] = 0.f; p2[t] = 0.f; }
            const float2* wr = wz + w*64;
            const float* xb = xs + lane;
            #pragma unroll 4
            for (int ci = 0; ci < 64; ++ci) {
                float2 wv = wr[ci];
                const float* xc = xb + ci*200;
                #pragma unroll
                for (int t = 0; t < 8; ++t) {
                    float xv = xc[t*25];
                    p1[t] += wv.x * xv;
                    p2[t] += wv.y * xv;
                }
            }
            #pragma unroll
            for (int t = 0; t < 8; ++t) {
                float f = p1[t] + b1r, g = p2[t] + b2r;
                part1 += f; q1 += f*f;
                part2 += g; q2 += g*g;
            }
        }
        __syncthreads();
    }

    if (lane < 25) {
        g_part1[(n*4 + split)*200 + w*25 + lane] = part1;
        g_part2[(n*4 + split)*200 + w*25 + lane] = part2;
    } else {
        part1 = 0.f; part2 = 0.f; q1 = 0.f; q2 = 0.f;
    }
    float s1 = part1, s2 = part2;
    #pragma unroll
    for (int off = 16; off; off >>= 1) {
        s1 += __shfl_xor_sync(0xffffffffu, s1, off);
        q1 += __shfl_xor_sync(0xffffffffu, q1, off);
        s2 += __shfl_xor_sync(0xffffffffu, s2, off);
        q2 += __shfl_xor_sync(0xffffffffu, q2, off);
    }
    if (lane == 0) { red[w*4+0]=s1; red[w*4+1]=q1; red[w*4+2]=s2; red[w*4+3]=q2; }
    __syncthreads();
    if (tid < 4) {
        float acc = 0.f;
        #pragma unroll
        for (int ww = 0; ww < 8; ++ww) acc += red[ww*4 + tid];
        g_pstat[(n*4 + split)*4 + tid] = acc;
    }
}

// ============================================================
// Kernel B: per-sample finalize -> ysum (padded stride 640).
// ============================================================
__global__ void __launch_bounds__(256) kB(const float* __restrict__ Aadj,
    const float* __restrict__ g1, const float* __restrict__ be1,
    const float* __restrict__ g2, const float* __restrict__ be2,
    const float* __restrict__ w4, const float* __restrict__ b4)
{
    __shared__ float x1s[200], x2s[200], yss[5000], w4s[512], st[4];
    int n = blockIdx.x, tid = threadIdx.x;

    if (tid < 4) {
        float s = 0.f;
        for (int k = 0; k < 4; ++k) s += g_pstat[(n*4 + k)*4 + tid];
        st[tid] = s;
    }
    for (int i = tid; i < 512; i += 256) w4s[i] = w4[i];
    float sum1 = 0.f, sum2 = 0.f;
    if (tid < 200) {
        for (int k = 0; k < 4; ++k) {
            sum1 += g_part1[(n*4 + k)*200 + tid];
            sum2 += g_part2[(n*4 + k)*200 + tid];
        }
    }
    __syncthreads();
    if (tid < 200) {
        const float inv = 1.0f / 25600.0f;     // R*T*V
        float mu1 = st[0]*inv, var1 = st[1]*inv - mu1*mu1;
        float mu2 = st[2]*inv, var2 = st[3]*inv - mu2*mu2;
        float rs1 = rsqrtf(var1 + 1e-5f), rs2 = rsqrtf(var2 + 1e-5f);
        int r = tid / 25;
        x1s[tid] = (sum1*(1.0f/128.0f) - mu1)*rs1*g1[r] + be1[r];
        x2s[tid] = (sum2*(1.0f/128.0f) - mu2)*rs2*g2[r] + be2[r];
    }
    __syncthreads();
    for (int i = tid; i < 5000; i += 256) {
        int r = i / 625, rem = i - r*625;
        int u = rem / 25, v = rem - u*25;
        yss[i] = tanhf(x1s[r*25+u] - x1s[r*25+v])
               + tanhf(x2s[r*25+u] * x2s[r*25+v])
               + __ldg(Aadj + rem);
    }
    __syncthreads();
    float* dst = g_ysum + (size_t)n*OO*YSTR;
    for (int i = tid; i < 40000; i += 256) {
        int c = i / 625, p = i - c*625;
        float a = b4[c];
        #pragma unroll
        for (int r = 0; r < 8; ++r) a += w4s[c*8 + r]*yss[r*625 + p];
        dst[c*YSTR + p] = a;
    }
}

// ============================================================
// Kernel C v5: phase 1+2 as before; phase 3 now also stages the
// OUTPUT through warp-private smem so stores go out as 50 coalesced
// float4 per (warp,cc) instead of 200 scalar STG.32 with 100B lane
// stride (~80x fewer L1tex write wavefronts).
// grid (16 t-tiles of 8, 128 n), 256 threads, 2 CTAs/SM, 90KB smem.
// ============================================================
__global__ void __launch_bounds__(256, 2) kC(const float* __restrict__ x,
    const float* __restrict__ w3, const float* __restrict__ b3,
    float* __restrict__ out)
{
    u64*   w3ps = (u64*)smem_raw;          // 4096 u64  [ci][64c]  (32KB)
    float* ybuf = (float*)smem_raw;        // alias after phase 2: [8 warps][640]
    float* xbuf = (float*)(w3ps + 4096);   // 64*224 floats (x, then x3 in place)

    int tid = threadIdx.x;
    int tt = blockIdx.x, n = blockIdx.y;
    int w = tid >> 5, lane = tid & 31;

    for (int i = tid; i < 4096; i += 256) {
        int c = i >> 6, ci = i & 63;
        float wv = w3[i];                   // w3[c][ci]
        w3ps[ci*64 + c] = pk2(wv, wv);
    }
    // load x tile: 64ci x 200 pos, scatter into padded [t*28+v] layout
    const float4* xn4 = (const float4*)(x + (size_t)n*CIN*TVPOS + tt*200);
    for (int i = tid; i < 3200; i += 256) {
        int ci = i / 50, j = i - ci*50;
        float4 v4 = xn4[ci*800 + j];
        int p = 4*j;
        float e[4] = {v4.x, v4.y, v4.z, v4.w};
        #pragma unroll
        for (int k = 0; k < 4; ++k) {
            int pp = p + k;
            int t = div25(pp), v = pp - t*25;
            xbuf[ci*224 + t*28 + v] = e[k];
        }
    }
    for (int i = tid; i < 1536; i += 256) {   // zero the 3-wide v pads
        int ci = i / 24, r = i - ci*24;
        int t = r / 3;
        xbuf[ci*224 + t*28 + 25 + (r - t*3)] = 0.0f;
    }
    __syncthreads();

    // ---- phase 2: x3 = W3*x + b3, in place, two disjoint passes ----
    int c0 = w*8;
    #pragma unroll
    for (int pass = 0; pass < 2; ++pass) {
        int q = pass*28 + lane;             // float4 quad index within row
        bool act = (lane < 28);
        u64 acc[8][2];
        if (act) {
            #pragma unroll
            for (int j = 0; j < 8; ++j) {
                float bv = __ldg(b3 + c0 + j);
                acc[j][0] = pk2(bv, bv); acc[j][1] = acc[j][0];
            }
            #pragma unroll 4
            for (int ci = 0; ci < 64; ++ci) {
                ulonglong2 xv = *(const ulonglong2*)(xbuf + ci*224 + 4*q);
                const ulonglong2* wr = (const ulonglong2*)(w3ps + ci*64 + c0);
                ulonglong2 w01 = wr[0], w23 = wr[1], w45 = wr[2], w67 = wr[3];
                fma2(acc[0][0], w01.x, xv.x); fma2(acc[0][1], w01.x, xv.y);
                fma2(acc[1][0], w01.y, xv.x); fma2(acc[1][1], w01.y, xv.y);
                fma2(acc[2][0], w23.x, xv.x); fma2(acc[2][1], w23.x, xv.y);
                fma2(acc[3][0], w23.y, xv.x); fma2(acc[3][1], w23.y, xv.y);
                fma2(acc[4][0], w45.x, xv.x); fma2(acc[4][1], w45.x, xv.y);
                fma2(acc[5][0], w45.y, xv.x); fma2(acc[5][1], w45.y, xv.y);
                fma2(acc[6][0], w67.x, xv.x); fma2(acc[6][1], w67.x, xv.y);
                fma2(acc[7][0], w67.y, xv.x); fma2(acc[7][1], w67.y, xv.y);
            }
        }
        __syncthreads();                    // all reads of this range done
        if (act) {
            #pragma unroll
            for (int j = 0; j < 8; ++j) {
                u64* row = (u64*)(xbuf + (c0 + j)*224);
                row[2*q]     = acc[j][0];
                row[2*q + 1] = acc[j][1];
            }
        }
    }
    __syncthreads();    // x3 complete; w3ps dead -> ybuf alias live

    // ---- phase 3: out[c,t,u] = sum_v ysum[c,u,v]*x3[c,t,v] ----
    const float* ysrc = g_ysum + (size_t)n*OO*YSTR;
    float* myy = ybuf + w*YSTR;            // warp-private 640-float slice
    for (int cc = 0; cc < 8; ++cc) {
        int c = cc*8 + w;                   // this warp's channel
        // warp-private coalesced ysum stage: 640 floats = 160 float4, 5/lane
        const float4* s4 = (const float4*)(ysrc + (size_t)c*YSTR);
        float4* d4 = (float4*)myy;
        #pragma unroll
        for (int j = 0; j < 5; ++j) d4[j*32 + lane] = s4[j*32 + lane];
        __syncwarp();
        if (lane < 25) {
            const float* yr = myy + lane*25;   // u = lane, conflict-free LDS
            u64 yp[13];
            #pragma unroll
            for (int j = 0; j < 12; ++j) yp[j] = pk2(yr[2*j], yr[2*j+1]);
            yp[12] = pk2(yr[24], 0.0f);     // x3 pad holds b3, times 0 -> safe
            u64 acc2[8];
            #pragma unroll
            for (int t = 0; t < 8; ++t) acc2[t] = pk2(0.f, 0.f);
            const u64* xrow = (const u64*)(xbuf + c*224);
            #pragma unroll
            for (int j = 0; j < 13; ++j) {
                #pragma unroll
                for (int t = 0; t < 8; ++t)
                    fma2(acc2[t], yp[j], xrow[t*14 + j]);
            }
            // stage 8t x 25u result block into smem (consecutive addrs,
            // conflict-free); ysum data already consumed into yp regs.
            #pragma unroll
            for (int t = 0; t < 8; ++t) {
                float lo, hi; upk2(acc2[t], lo, hi);
                myy[t*25 + lane] = lo + hi;
            }
        }
        __syncwarp();
        // coalesced store: 200 contiguous floats = 50 float4 (16B-aligned:
        // base offset is a multiple of 200 floats = 800B)
        {
            const float4* m4 = (const float4*)myy;
            float4* od4 = (float4*)(out + (((size_t)n*64 + c)*128 + tt*8)*25);
            if (lane < 25) {
                od4[lane]      = m4[lane];
                od4[lane + 25] = m4[lane + 25];
            }
        }
        __syncwarp();                       // stores' source reads done before restage
    }
}

// ============================================================
extern "C" void kernel_launch(void* const* d_in, const int* in_sizes, int n_in,
                              void* d_out, int out_size)
{
    (void)in_sizes; (void)n_in; (void)out_size;
    const float* x   = (const float*)d_in[0];
    const float* A   = (const float*)d_in[1];
    const float* w1  = (const float*)d_in[2];
    const float* b1  = (const float*)d_in[3];
    const float* g1  = (const float*)d_in[4];
    const float* be1 = (const float*)d_in[5];
    const float* w2  = (const float*)d_in[6];
    const float* b2  = (const float*)d_in[7];
    const float* g2  = (const float*)d_in[8];
    const float* be2 = (const float*)d_in[9];
    const float* w3  = (const float*)d_in[10];
    const float* b3  = (const float*)d_in[11];
    const float* w4  = (const float*)d_in[12];
    const float* b4  = (const float*)d_in[13];
    float* out = (float*)d_out;

    const int smemA = 512*8 + 12800*4 + 32*4;    // 55424
    const int smemC = 4096*8 + 64*224*4;         // 90112
    cudaFuncSetAttribute(kA, cudaFuncAttributeMaxDynamicSharedMemorySize, smemA);
    cudaFuncSetAttribute(kC, cudaFuncAttributeMaxDynamicSharedMemorySize, smemC);

    kA<<<dim3(4, 128), 256, smemA>>>(x, w1, b1, w2, b2);
    kB<<<128, 256>>>(A, g1, be1, g2, be2, w4, b4);
    kC<<<dim3(16, 128), 256, smemC>>>(x, w3, b3, out);
}

// round 9
// speedup vs baseline: 1.0207x; 1.0207x over previous
#include <cuda_runtime.h>

#define NB   128
#define CIN  64
#define TDIM 128
#define VV   25
#define RR   8
#define OO   64
#define TVPOS 3200   // TDIM*VV
#define YSTR 640     // padded ysum channel stride (16B-aligned float4 staging)

typedef unsigned long long u64;

// ---- scratch (device globals: no allocation allowed) ----
__device__ float g_part1[NB*4*RR*VV];
__device__ float g_part2[NB*4*RR*VV];
__device__ float g_pstat[NB*4*4];
__device__ float g_ysum[(size_t)NB*OO*YSTR];   // [n][c][640], 625 used
__device__ float g_dummy[32];

// ---- packed fp32x2 helpers (FFMA2 only reachable via PTX) ----
__device__ __forceinline__ u64 pk2(float a, float b){
    u64 r; asm("mov.b64 %0,{%1,%2};" : "=l"(r) : "f"(a), "f"(b)); return r;
}
__device__ __forceinline__ void upk2(u64 v, float& a, float& b){
    asm("mov.b64 {%0,%1},%2;" : "=f"(a), "=f"(b) : "l"(v));
}
__device__ __forceinline__ void fma2(u64& d, u64 a, u64 b){
    asm("fma.rn.f32x2 %0,%1,%2,%0;" : "+l"(d) : "l"(a), "l"(b));
}

__device__ __forceinline__ int div25(int p){ return (p*1311) >> 15; }  // valid p<256

extern __shared__ char smem_raw[];

// ---- dummy: shifts ncu capture index so the profiled launch is kC ----
__global__ void kDummy() { g_dummy[threadIdx.x & 31] = 0.0f; }

// ============================================================
// Kernel A (frozen, ~60us): stats pass, no atomics.
// grid (4 splits, 128 n), 256 thr.  warp->r, lane->v (lane<25).
// ============================================================
__global__ void __launch_bounds__(256, 4) kA(const float* __restrict__ x,
        const float* __restrict__ w1, const float* __restrict__ b1,
        const float* __restrict__ w2, const float* __restrict__ b2)
{
    float2* wz = (float2*)smem_raw;        // [8][64] packed (w1,w2)
    float*  xs = (float*)(wz + 512);       // [64][200]
    float*  red = xs + 12800;              // [8][4]

    int tid = threadIdx.x;
    int split = blockIdx.x, n = blockIdx.y;
    int w = tid >> 5, lane = tid & 31;

    for (int i = tid; i < 512; i += 256)
        wz[i] = make_float2(w1[i], w2[i]);

    float b1r = b1[w], b2r = b2[w];
    float part1 = 0.f, part2 = 0.f, q1 = 0.f, q2 = 0.f;
    const float4* xn4 = (const float4*)(x + (size_t)n*CIN*TVPOS + split*800);
    __syncthreads();

    for (int tile = 0; tile < 4; ++tile) {
        for (int i = tid; i < 3200; i += 256) {
            int ci = i / 50, j = i - ci*50;
            ((float4*)xs)[ci*50 + j] = xn4[ci*800 + tile*50 + j];
        }
        __syncthreads();
        if (lane < 25) {
            float p1[8], p2[8];
            #pragma unroll
            for (int t = 0; t < 8; ++t) { p1[t] = 0.f; p2[t] = 0.f; }
            const float2* wr = wz + w*64;
            const float* xb = xs + lane;
            #pragma unroll 4
            for (int ci = 0; ci < 64; ++ci) {
                float2 wv = wr[ci];
                const float* xc = xb + ci*200;
                #pragma unroll
                for (int t = 0; t < 8; ++t) {
                    float xv = xc[t*25];
                    p1[t] += wv.x * xv;
                    p2[t] += wv.y * xv;
                }
            }
            #pragma unroll
            for (int t = 0; t < 8; ++t) {
                float f = p1[t] + b1r, g = p2[t] + b2r;
                part1 += f; q1 += f*f;
                part2 += g; q2 += g*g;
            }
        }
        __syncthreads();
    }

    if (lane < 25) {
        g_part1[(n*4 + split)*200 + w*25 + lane] = part1;
        g_part2[(n*4 + split)*200 + w*25 + lane] = part2;
    } else {
        part1 = 0.f; part2 = 0.f; q1 = 0.f; q2 = 0.f;
    }
    float s1 = part1, s2 = part2;
    #pragma unroll
    for (int off = 16; off; off >>= 1) {
        s1 += __shfl_xor_sync(0xffffffffu, s1, off);
        q1 += __shfl_xor_sync(0xffffffffu, q1, off);
        s2 += __shfl_xor_sync(0xffffffffu, s2, off);
        q2 += __shfl_xor_sync(0xffffffffu, q2, off);
    }
    if (lane == 0) { red[w*4+0]=s1; red[w*4+1]=q1; red[w*4+2]=s2; red[w*4+3]=q2; }
    __syncthreads();
    if (tid < 4) {
        float acc = 0.f;
        #pragma unroll
        for (int ww = 0; ww < 8; ++ww) acc += red[ww*4 + tid];
        g_pstat[(n*4 + split)*4 + tid] = acc;
    }
}

// ============================================================
// Kernel B: per-sample finalize -> ysum (padded stride 640).
// ============================================================
__global__ void __launch_bounds__(256) kB(const float* __restrict__ Aadj,
    const float* __restrict__ g1, const float* __restrict__ be1,
    const float* __restrict__ g2, const float* __restrict__ be2,
    const float* __restrict__ w4, const float* __restrict__ b4)
{
    __shared__ float x1s[200], x2s[200], yss[5000], w4s[512], st[4];
    int n = blockIdx.x, tid = threadIdx.x;

    if (tid < 4) {
        float s = 0.f;
        for (int k = 0; k < 4; ++k) s += g_pstat[(n*4 + k)*4 + tid];
        st[tid] = s;
    }
    for (int i = tid; i < 512; i += 256) w4s[i] = w4[i];
    float sum1 = 0.f, sum2 = 0.f;
    if (tid < 200) {
        for (int k = 0; k < 4; ++k) {
            sum1 += g_part1[(n*4 + k)*200 + tid];
            sum2 += g_part2[(n*4 + k)*200 + tid];
        }
    }
    __syncthreads();
    if (tid < 200) {
        const float inv = 1.0f / 25600.0f;     // R*T*V
        float mu1 = st[0]*inv, var1 = st[1]*inv - mu1*mu1;
        float mu2 = st[2]*inv, var2 = st[3]*inv - mu2*mu2;
        float rs1 = rsqrtf(var1 + 1e-5f), rs2 = rsqrtf(var2 + 1e-5f);
        int r = tid / 25;
        x1s[tid] = (sum1*(1.0f/128.0f) - mu1)*rs1*g1[r] + be1[r];
        x2s[tid] = (sum2*(1.0f/128.0f) - mu2)*rs2*g2[r] + be2[r];
    }
    __syncthreads();
    for (int i = tid; i < 5000; i += 256) {
        int r = i / 625, rem = i - r*625;
        int u = rem / 25, v = rem - u*25;
        yss[i] = tanhf(x1s[r*25+u] - x1s[r*25+v])
               + tanhf(x2s[r*25+u] * x2s[r*25+v])
               + __ldg(Aadj + rem);
    }
    __syncthreads();
    float* dst = g_ysum + (size_t)n*OO*YSTR;
    for (int i = tid; i < 40000; i += 256) {
        int c = i / 625, p = i - c*625;
        float a = b4[c];
        #pragma unroll
        for (int r = 0; r < 8; ++r) a += w4s[c*8 + r]*yss[r*625 + p];
        dst[c*YSTR + p] = a;
    }
}

// ============================================================
// Kernel C v6: as v5, plus register software-pipeline on the
// phase-3 ysum staging loads (prefetch next channel's 5 float4
// during current channel's compute -> L2 latency hidden).
// grid (16 t-tiles of 8, 128 n), 256 threads, 2 CTAs/SM, 90KB smem.
// ============================================================
__global__ void __launch_bounds__(256, 2) kC(const float* __restrict__ x,
    const float* __restrict__ w3, const float* __restrict__ b3,
    float* __restrict__ out)
{
    u64*   w3ps = (u64*)smem_raw;          // 4096 u64  [ci][64c]  (32KB)
    float* ybuf = (float*)smem_raw;        // alias after phase 2: [8 warps][640]
    float* xbuf = (float*)(w3ps + 4096);   // 64*224 floats (x, then x3 in place)

    int tid = threadIdx.x;
    int tt = blockIdx.x, n = blockIdx.y;
    int w = tid >> 5, lane = tid & 31;

    for (int i = tid; i < 4096; i += 256) {
        int c = i >> 6, ci = i & 63;
        float wv = w3[i];                   // w3[c][ci]
        w3ps[ci*64 + c] = pk2(wv, wv);
    }
    // load x tile: 64ci x 200 pos, scatter into padded [t*28+v] layout
    const float4* xn4 = (const float4*)(x + (size_t)n*CIN*TVPOS + tt*200);
    for (int i = tid; i < 3200; i += 256) {
        int ci = i / 50, j = i - ci*50;
        float4 v4 = xn4[ci*800 + j];
        int p = 4*j;
        float e[4] = {v4.x, v4.y, v4.z, v4.w};
        #pragma unroll
        for (int k = 0; k < 4; ++k) {
            int pp = p + k;
            int t = div25(pp), v = pp - t*25;
            xbuf[ci*224 + t*28 + v] = e[k];
        }
    }
    for (int i = tid; i < 1536; i += 256) {   // zero the 3-wide v pads
        int ci = i / 24, r = i - ci*24;
        int t = r / 3;
        xbuf[ci*224 + t*28 + 25 + (r - t*3)] = 0.0f;
    }
    __syncthreads();

    // ---- phase 2: x3 = W3*x + b3, in place, two disjoint passes ----
    int c0 = w*8;
    #pragma unroll
    for (int pass = 0; pass < 2; ++pass) {
        int q = pass*28 + lane;             // float4 quad index within row
        bool act = (lane < 28);
        u64 acc[8][2];
        if (act) {
            #pragma unroll
            for (int j = 0; j < 8; ++j) {
                float bv = __ldg(b3 + c0 + j);
                acc[j][0] = pk2(bv, bv); acc[j][1] = acc[j][0];
            }
            #pragma unroll 4
            for (int ci = 0; ci < 64; ++ci) {
                ulonglong2 xv = *(const ulonglong2*)(xbuf + ci*224 + 4*q);
                const ulonglong2* wr = (const ulonglong2*)(w3ps + ci*64 + c0);
                ulonglong2 w01 = wr[0], w23 = wr[1], w45 = wr[2], w67 = wr[3];
                fma2(acc[0][0], w01.x, xv.x); fma2(acc[0][1], w01.x, xv.y);
                fma2(acc[1][0], w01.y, xv.x); fma2(acc[1][1], w01.y, xv.y);
                fma2(acc[2][0], w23.x, xv.x); fma2(acc[2][1], w23.x, xv.y);
                fma2(acc[3][0], w23.y, xv.x); fma2(acc[3][1], w23.y, xv.y);
                fma2(acc[4][0], w45.x, xv.x); fma2(acc[4][1], w45.x, xv.y);
                fma2(acc[5][0], w45.y, xv.x); fma2(acc[5][1], w45.y, xv.y);
                fma2(acc[6][0], w67.x, xv.x); fma2(acc[6][1], w67.x, xv.y);
                fma2(acc[7][0], w67.y, xv.x); fma2(acc[7][1], w67.y, xv.y);
            }
        }
        __syncthreads();                    // all reads of this range done
        if (act) {
            #pragma unroll
            for (int j = 0; j < 8; ++j) {
                u64* row = (u64*)(xbuf + (c0 + j)*224);
                row[2*q]     = acc[j][0];
                row[2*q + 1] = acc[j][1];
            }
        }
    }
    __syncthreads();    // x3 complete; w3ps dead -> ybuf alias live

    // ---- phase 3: out[c,t,u] = sum_v ysum[c,u,v]*x3[c,t,v],
    //      ysum stage software-pipelined in registers ----
    const float* ysrc = g_ysum + (size_t)n*OO*YSTR;
    float* myy = ybuf + w*YSTR;            // warp-private 640-float slice
    float4 pf0, pf1, pf2, pf3, pf4;
    {
        const float4* s4 = (const float4*)(ysrc + (size_t)w*YSTR);
        pf0 = s4[lane]; pf1 = s4[32+lane]; pf2 = s4[64+lane];
        pf3 = s4[96+lane]; pf4 = s4[128+lane];
    }
    for (int cc = 0; cc < 8; ++cc) {
        int c = cc*8 + w;                   // this warp's channel
        {   // commit prefetched stage (prev compute's myy reads are done:
            // program order within lane + syncwarp at loop tail)
            float4* d4 = (float4*)myy;
            d4[lane] = pf0; d4[32+lane] = pf1; d4[64+lane] = pf2;
            d4[96+lane] = pf3; d4[128+lane] = pf4;
        }
        if (cc < 7) {                       // prefetch next channel
            const float4* s4 = (const float4*)(ysrc + (size_t)(c + 8)*YSTR);
            pf0 = s4[lane]; pf1 = s4[32+lane]; pf2 = s4[64+lane];
            pf3 = s4[96+lane]; pf4 = s4[128+lane];
        }
        __syncwarp();
        if (lane < 25) {
            const float* yr = myy + lane*25;   // u = lane, conflict-free LDS
            u64 yp[13];
            #pragma unroll
            for (int j = 0; j < 12; ++j) yp[j] = pk2(yr[2*j], yr[2*j+1]);
            yp[12] = pk2(yr[24], 0.0f);     // x3 pad holds b3, times 0 -> safe
            u64 acc2[8];
            #pragma unroll
            for (int t = 0; t < 8; ++t) acc2[t] = pk2(0.f, 0.f);
            const u64* xrow = (const u64*)(xbuf + c*224);
            #pragma unroll
            for (int j = 0; j < 13; ++j) {
                #pragma unroll
                for (int t = 0; t < 8; ++t)
                    fma2(acc2[t], yp[j], xrow[t*14 + j]);
            }
            // stage 8t x 25u result block into smem (consecutive, conflict-free)
            #pragma unroll
            for (int t = 0; t < 8; ++t) {
                float lo, hi; upk2(acc2[t], lo, hi);
                myy[t*25 + lane] = lo + hi;
            }
        }
        __syncwarp();
        // coalesced store: 200 contiguous floats = 50 float4
        {
            const float4* m4 = (const float4*)myy;
            float4* od4 = (float4*)(out + (((size_t)n*64 + c)*128 + tt*8)*25);
            if (lane < 25) {
                od4[lane]      = m4[lane];
                od4[lane + 25] = m4[lane + 25];
            }
        }
        __syncwarp();                       // stores' source reads done before restage
    }
}

// ============================================================
extern "C" void kernel_launch(void* const* d_in, const int* in_sizes, int n_in,
                              void* d_out, int out_size)
{
    (void)in_sizes; (void)n_in; (void)out_size;
    const float* x   = (const float*)d_in[0];
    const float* A   = (const float*)d_in[1];
    const float* w1  = (const float*)d_in[2];
    const float* b1  = (const float*)d_in[3];
    const float* g1  = (const float*)d_in[4];
    const float* be1 = (const float*)d_in[5];
    const float* w2  = (const float*)d_in[6];
    const float* b2  = (const float*)d_in[7];
    const float* g2  = (const float*)d_in[8];
    const float* be2 = (const float*)d_in[9];
    const float* w3  = (const float*)d_in[10];
    const float* b3  = (const float*)d_in[11];
    const float* w4  = (const float*)d_in[12];
    const float* b4  = (const float*)d_in[13];
    float* out = (float*)d_out;

    const int smemA = 512*8 + 12800*4 + 32*4;    // 55424
    const int smemC = 4096*8 + 64*224*4;         // 90112
    cudaFuncSetAttribute(kA, cudaFuncAttributeMaxDynamicSharedMemorySize, smemA);
    cudaFuncSetAttribute(kC, cudaFuncAttributeMaxDynamicSharedMemorySize, smemC);

    kDummy<<<1, 32>>>();   // shifts ncu -s 5 -c 1 capture onto kC
    kA<<<dim3(4, 128), 256, smemA>>>(x, w1, b1, w2, b2);
    kB<<<128, 256>>>(A, g1, be1, g2, be2, w4, b4);
    kC<<<dim3(16, 128), 256, smemC>>>(x, w3, b3, out);
}

// round 10
// speedup vs baseline: 1.0848x; 1.0628x over previous
#include <cuda_runtime.h>

#define NB   128
#define CIN  64
#define TDIM 128
#define VV   25
#define RR   8
#define OO   64
#define TVPOS 3200   // TDIM*VV

typedef unsigned long long u64;

// ---- scratch (device globals: no allocation allowed) ----
__device__ float g_part1[NB*4*RR*VV];
__device__ float g_part2[NB*4*RR*VV];
__device__ float g_pstat[NB*4*4];
// ysum as v-pairs: [n][c][j=0..12][u=0..31(pad)] u64 = (y[u][2j], y[u][2j+1])
__device__ u64   g_y2[(size_t)NB*OO*13*32];
__device__ float g_dummy[32];

// ---- packed fp32x2 helpers (FFMA2 only reachable via PTX) ----
__device__ __forceinline__ u64 pk2(float a, float b){
    u64 r; asm("mov.b64 %0,{%1,%2};" : "=l"(r) : "f"(a), "f"(b)); return r;
}
__device__ __forceinline__ void upk2(u64 v, float& a, float& b){
    asm("mov.b64 {%0,%1},%2;" : "=f"(a), "=f"(b) : "l"(v));
}
__device__ __forceinline__ void fma2(u64& d, u64 a, u64 b){
    asm("fma.rn.f32x2 %0,%1,%2,%0;" : "+l"(d) : "l"(a), "l"(b));
}

__device__ __forceinline__ int div25(int p){ return (p*1311) >> 15; }  // valid p<256

extern __shared__ char smem_raw[];

// ---- dummy: shifts ncu capture index so the profiled launch is kC ----
__global__ void kDummy() { g_dummy[threadIdx.x & 31] = 0.0f; }

// ============================================================
// Kernel A (frozen, ~60us): stats pass, no atomics.
// ============================================================
__global__ void __launch_bounds__(256, 4) kA(const float* __restrict__ x,
        const float* __restrict__ w1, const float* __restrict__ b1,
        const float* __restrict__ w2, const float* __restrict__ b2)
{
    float2* wz = (float2*)smem_raw;        // [8][64] packed (w1,w2)
    float*  xs = (float*)(wz + 512);       // [64][200]
    float*  red = xs + 12800;              // [8][4]

    int tid = threadIdx.x;
    int split = blockIdx.x, n = blockIdx.y;
    int w = tid >> 5, lane = tid & 31;

    for (int i = tid; i < 512; i += 256)
        wz[i] = make_float2(w1[i], w2[i]);

    float b1r = b1[w], b2r = b2[w];
    float part1 = 0.f, part2 = 0.f, q1 = 0.f, q2 = 0.f;
    const float4* xn4 = (const float4*)(x + (size_t)n*CIN*TVPOS + split*800);
    __syncthreads();

    for (int tile = 0; tile < 4; ++tile) {
        for (int i = tid; i < 3200; i += 256) {
            int ci = i / 50, j = i - ci*50;
            ((float4*)xs)[ci*50 + j] = xn4[ci*800 + tile*50 + j];
        }
        __syncthreads();
        if (lane < 25) {
            float p1[8], p2[8];
            #pragma unroll
            for (int t = 0; t < 8; ++t) { p1[t] = 0.f; p2[t] = 0.f; }
            const float2* wr = wz + w*64;
            const float* xb = xs + lane;
            #pragma unroll 4
            for (int ci = 0; ci < 64; ++ci) {
                float2 wv = wr[ci];
                const float* xc = xb + ci*200;
                #pragma unroll
                for (int t = 0; t < 8; ++t) {
                    float xv = xc[t*25];
                    p1[t] += wv.x * xv;
                    p2[t] += wv.y * xv;
                }
            }
            #pragma unroll
            for (int t = 0; t < 8; ++t) {
                float f = p1[t] + b1r, g = p2[t] + b2r;
                part1 += f; q1 += f*f;
                part2 += g; q2 += g*g;
            }
        }
        __syncthreads();
    }

    if (lane < 25) {
        g_part1[(n*4 + split)*200 + w*25 + lane] = part1;
        g_part2[(n*4 + split)*200 + w*25 + lane] = part2;
    } else {
        part1 = 0.f; part2 = 0.f; q1 = 0.f; q2 = 0.f;
    }
    float s1 = part1, s2 = part2;
    #pragma unroll
    for (int off = 16; off; off >>= 1) {
        s1 += __shfl_xor_sync(0xffffffffu, s1, off);
        q1 += __shfl_xor_sync(0xffffffffu, q1, off);
        s2 += __shfl_xor_sync(0xffffffffu, s2, off);
        q2 += __shfl_xor_sync(0xffffffffu, q2, off);
    }
    if (lane == 0) { red[w*4+0]=s1; red[w*4+1]=q1; red[w*4+2]=s2; red[w*4+3]=q2; }
    __syncthreads();
    if (tid < 4) {
        float acc = 0.f;
        #pragma unroll
        for (int ww = 0; ww < 8; ++ww) acc += red[ww*4 + tid];
        g_pstat[(n*4 + split)*4 + tid] = acc;
    }
}

// ============================================================
// Kernel B: per-sample finalize -> g_y2 v-pair layout
// [c][j][u] u64 = (ysum[c][u][2j], ysum[c][u][2j+1] or 0).
// ============================================================
__global__ void __launch_bounds__(256) kB(const float* __restrict__ Aadj,
    const float* __restrict__ g1, const float* __restrict__ be1,
    const float* __restrict__ g2, const float* __restrict__ be2,
    const float* __restrict__ w4, const float* __restrict__ b4)
{
    __shared__ float x1s[200], x2s[200], yss[5000], w4s[512], st[4];
    int n = blockIdx.x, tid = threadIdx.x;

    if (tid < 4) {
        float s = 0.f;
        for (int k = 0; k < 4; ++k) s += g_pstat[(n*4 + k)*4 + tid];
        st[tid] = s;
    }
    for (int i = tid; i < 512; i += 256) w4s[i] = w4[i];
    float sum1 = 0.f, sum2 = 0.f;
    if (tid < 200) {
        for (int k = 0; k < 4; ++k) {
            sum1 += g_part1[(n*4 + k)*200 + tid];
            sum2 += g_part2[(n*4 + k)*200 + tid];
        }
    }
    __syncthreads();
    if (tid < 200) {
        const float inv = 1.0f / 25600.0f;     // R*T*V
        float mu1 = st[0]*inv, var1 = st[1]*inv - mu1*mu1;
        float mu2 = st[2]*inv, var2 = st[3]*inv - mu2*mu2;
        float rs1 = rsqrtf(var1 + 1e-5f), rs2 = rsqrtf(var2 + 1e-5f);
        int r = tid / 25;
        x1s[tid] = (sum1*(1.0f/128.0f) - mu1)*rs1*g1[r] + be1[r];
        x2s[tid] = (sum2*(1.0f/128.0f) - mu2)*rs2*g2[r] + be2[r];
    }
    __syncthreads();
    for (int i = tid; i < 5000; i += 256) {
        int r = i / 625, rem = i - r*625;
        int u = rem / 25, v = rem - u*25;
        yss[i] = tanhf(x1s[r*25+u] - x1s[r*25+v])
               + tanhf(x2s[r*25+u] * x2s[r*25+v])
               + __ldg(Aadj + rem);
    }
    __syncthreads();
    // build v-pairs: i = c*416 + j*32 + u
    u64* dst = g_y2 + (size_t)n*OO*416;
    for (int i = tid; i < OO*416; i += 256) {
        int c = i / 416, rem = i - c*416;
        int j = rem >> 5, u = rem & 31;
        float a = 0.f, b = 0.f;
        if (u < 25) {
            int p0 = u*25 + 2*j;
            a = b4[c];
            #pragma unroll
            for (int r = 0; r < 8; ++r) a += w4s[c*8 + r]*yss[r*625 + p0];
            if (2*j + 1 < 25) {
                b = b4[c];
                #pragma unroll
                for (int r = 0; r < 8; ++r) b += w4s[c*8 + r]*yss[r*625 + p0 + 1];
            }
        }
        dst[i] = pk2(a, b);
    }
}

// ============================================================
// Kernel C v7:
//  phase 2: FUSED single ci-loop (weights loaded once per ci,
//           both quad-halves accumulated; one sync, in-place store)
//  phase 3: yp via 13 coalesced LDG.64 from g_y2 (no staging),
//           x3 via broadcast LDS.128, warp-aligned channels,
//           output staged in dead-w3 smem then float4 stores.
// grid (16 t-tiles of 8, 128 n), 256 threads, 2 CTAs/SM, 90KB smem.
// ============================================================
__global__ void __launch_bounds__(256, 2) kC(const float* __restrict__ x,
    const float* __restrict__ w3, const float* __restrict__ b3,
    float* __restrict__ out)
{
    u64*   w3ps = (u64*)smem_raw;          // 4096 u64 [ci][64c] (32KB)
    float* ost  = (float*)smem_raw;        // alias after phase 2: [8 warps][256]
    float* xbuf = (float*)(w3ps + 4096);   // 64*224 floats (x, then x3 in place)

    int tid = threadIdx.x;
    int tt = blockIdx.x, n = blockIdx.y;
    int w = tid >> 5, lane = tid & 31;

    for (int i = tid; i < 4096; i += 256) {
        int c = i >> 6, ci = i & 63;
        float wv = w3[i];                   // w3[c][ci]
        w3ps[ci*64 + c] = pk2(wv, wv);
    }
    // load x tile: 64ci x 200 pos, scatter into padded [t*28+v] layout
    const float4* xn4 = (const float4*)(x + (size_t)n*CIN*TVPOS + tt*200);
    for (int i = tid; i < 3200; i += 256) {
        int ci = i / 50, j = i - ci*50;
        float4 v4 = xn4[ci*800 + j];
        int p = 4*j;
        float e[4] = {v4.x, v4.y, v4.z, v4.w};
        #pragma unroll
        for (int k = 0; k < 4; ++k) {
            int pp = p + k;
            int t = div25(pp), v = pp - t*25;
            xbuf[ci*224 + t*28 + v] = e[k];
        }
    }
    for (int i = tid; i < 1536; i += 256) {   // zero the 3-wide v pads
        int ci = i / 24, r = i - ci*24;
        int t = r / 3;
        xbuf[ci*224 + t*28 + 25 + (r - t*3)] = 0.0f;
    }
    __syncthreads();

    // ---- phase 2: x3 = W3*x + b3, fused, in place ----
    int c0 = w*8;
    bool act = (lane < 28);
    u64 acc[8][4];
    #pragma unroll
    for (int j = 0; j < 8; ++j) {
        float bv = __ldg(b3 + c0 + j);
        acc[j][0] = pk2(bv, bv);
        acc[j][1] = acc[j][0]; acc[j][2] = acc[j][0]; acc[j][3] = acc[j][0];
    }
    if (act) {
        #pragma unroll 4
        for (int ci = 0; ci < 64; ++ci) {
            ulonglong2 xv0 = *(const ulonglong2*)(xbuf + ci*224 + 4*lane);
            ulonglong2 xv1 = *(const ulonglong2*)(xbuf + ci*224 + 4*lane + 112);
            const ulonglong2* wr = (const ulonglong2*)(w3ps + ci*64 + c0);
            ulonglong2 w01 = wr[0], w23 = wr[1], w45 = wr[2], w67 = wr[3];
            fma2(acc[0][0], w01.x, xv0.x); fma2(acc[0][1], w01.x, xv0.y);
            fma2(acc[0][2], w01.x, xv1.x); fma2(acc[0][3], w01.x, xv1.y);
            fma2(acc[1][0], w01.y, xv0.x); fma2(acc[1][1], w01.y, xv0.y);
            fma2(acc[1][2], w01.y, xv1.x); fma2(acc[1][3], w01.y, xv1.y);
            fma2(acc[2][0], w23.x, xv0.x); fma2(acc[2][1], w23.x, xv0.y);
            fma2(acc[2][2], w23.x, xv1.x); fma2(acc[2][3], w23.x, xv1.y);
            fma2(acc[3][0], w23.y, xv0.x); fma2(acc[3][1], w23.y, xv0.y);
            fma2(acc[3][2], w23.y, xv1.x); fma2(acc[3][3], w23.y, xv1.y);
            fma2(acc[4][0], w45.x, xv0.x); fma2(acc[4][1], w45.x, xv0.y);
            fma2(acc[4][2], w45.x, xv1.x); fma2(acc[4][3], w45.x, xv1.y);
            fma2(acc[5][0], w45.y, xv0.x); fma2(acc[5][1], w45.y, xv0.y);
            fma2(acc[5][2], w45.y, xv1.x); fma2(acc[5][3], w45.y, xv1.y);
            fma2(acc[6][0], w67.x, xv0.x); fma2(acc[6][1], w67.x, xv0.y);
            fma2(acc[6][2], w67.x, xv1.x); fma2(acc[6][3], w67.x, xv1.y);
            fma2(acc[7][0], w67.y, xv0.x); fma2(acc[7][1], w67.y, xv0.y);
            fma2(acc[7][2], w67.y, xv1.x); fma2(acc[7][3], w67.y, xv1.y);
        }
    }
    __syncthreads();                        // all x reads done before overwrite
    if (act) {
        #pragma unroll
        for (int j = 0; j < 8; ++j) {
            u64* row = (u64*)(xbuf + (c0 + j)*224);
            row[2*lane]      = acc[j][0];
            row[2*lane + 1]  = acc[j][1];
            row[2*lane + 56] = acc[j][2];
            row[2*lane + 57] = acc[j][3];
        }
    }
    __syncthreads();    // x3 complete; w3ps dead -> ost alias live

    // ---- phase 3: out[c,t,u] = sum_v ysum[c,u,v]*x3[c,t,v] ----
    const u64* ysrc = g_y2 + (size_t)n*OO*416;
    float* myo = ost + w*256;               // warp-private output stage
    for (int cc = 0; cc < 8; ++cc) {
        int c = c0 + cc;                    // warp's own phase-2 channels
        u64 yp[13];
        const u64* yb = ysrc + (size_t)c*416 + lane;
        #pragma unroll
        for (int j = 0; j < 13; ++j) yp[j] = yb[j*32];   // coalesced LDG.64
        if (lane < 25) {
            const ulonglong2* xr = (const ulonglong2*)(xbuf + c*224);
            u64 acc2[8];
            #pragma unroll
            for (int t = 0; t < 8; ++t) acc2[t] = pk2(0.f, 0.f);
            #pragma unroll
            for (int t = 0; t < 8; ++t) {
                #pragma unroll
                for (int j2 = 0; j2 < 6; ++j2) {
                    ulonglong2 X = xr[t*7 + j2];        // broadcast LDS.128
                    fma2(acc2[t], yp[2*j2],     X.x);
                    fma2(acc2[t], yp[2*j2 + 1], X.y);
                }
                ulonglong2 X6 = xr[t*7 + 6];
                fma2(acc2[t], yp[12], X6.x);            // v=24 (+0*v25)
            }
            #pragma unroll
            for (int t = 0; t < 8; ++t) {
                float lo, hi; upk2(acc2[t], lo, hi);
                myo[t*25 + lane] = lo + hi;
            }
        }
        __syncwarp();
        {   // coalesced store: 200 contiguous floats = 50 float4
            const float4* m4 = (const float4*)myo;
            float4* od4 = (float4*)(out + (((size_t)n*64 + c)*128 + tt*8)*25);
            if (lane < 25) {
                od4[lane]      = m4[lane];
                od4[lane + 25] = m4[lane + 25];
            }
        }
        __syncwarp();                       // stage reads done before reuse
    }
}

// ============================================================
extern "C" void kernel_launch(void* const* d_in, const int* in_sizes, int n_in,
                              void* d_out, int out_size)
{
    (void)in_sizes; (void)n_in; (void)out_size;
    const float* x   = (const float*)d_in[0];
    const float* A   = (const float*)d_in[1];
    const float* w1  = (const float*)d_in[2];
    const float* b1  = (const float*)d_in[3];
    const float* g1  = (const float*)d_in[4];
    const float* be1 = (const float*)d_in[5];
    const float* w2  = (const float*)d_in[6];
    const float* b2  = (const float*)d_in[7];
    const float* g2  = (const float*)d_in[8];
    const float* be2 = (const float*)d_in[9];
    const float* w3  = (const float*)d_in[10];
    const float* b3  = (const float*)d_in[11];
    const float* w4  = (const float*)d_in[12];
    const float* b4  = (const float*)d_in[13];
    float* out = (float*)d_out;

    const int smemA = 512*8 + 12800*4 + 32*4;    // 55424
    const int smemC = 4096*8 + 64*224*4;         // 90112
    cudaFuncSetAttribute(kA, cudaFuncAttributeMaxDynamicSharedMemorySize, smemA);
    cudaFuncSetAttribute(kC, cudaFuncAttributeMaxDynamicSharedMemorySize, smemC);

    kDummy<<<1, 32>>>();   // shifts ncu -s 5 -c 1 capture onto kC
    kA<<<dim3(4, 128), 256, smemA>>>(x, w1, b1, w2, b2);
    kB<<<128, 256>>>(A, g1, be1, g2, be2, w4, b4);
    kC<<<dim3(16, 128), 256, smemC>>>(x, w3, b3, out);
}